// round 5
// baseline (speedup 1.0000x reference)
#include <cuda_runtime.h>
#include <cstdint>

// Problem constants
#define BATCH 512
#define INF   4096
#define OUTF  4096

// GEMM tiling: CTA 128x128, K-chunk 32 fp32. Warp grid 2(M) x 4(N), warp tile 64x32.
#define TM 128
#define TN 128
#define KC 32
#define ITERS (INF / KC)          // 128
#define STAGES 4
#define AS_STRIDE 36              // 32 + 4 pad floats -> conflict-free LDSM row pointers
#define TILE_FLOATS (128 * AS_STRIDE)           // 4608 floats
#define STAGE_BYTES (2 * TILE_FLOATS * 4)       // A + B = 36864 B
#define SMEM_BYTES (STAGES * STAGE_BYTES)       // 147456 B

#define GEMM_CTAS 128
#define PROD_CTAS 20
#define ROWS_PER_PROD 205         // ceil(4096 / 20)

// Scratch + handshake (device globals are the sanctioned scratch mechanism)
__device__ float g_W[(size_t)OUTF * INF];   // dequantized weight, tf32-rounded (64 MB)
__device__ int   g_flag[ITERS];             // per-k-chunk producer counters

// ---------------- PTX helpers (plain-sm_103 legal) ----------------
__device__ __forceinline__ uint32_t smem_u32(const void* p) {
    uint32_t a;
    asm("{ .reg .u64 t; cvta.to.shared.u64 t, %1; cvt.u32.u64 %0, t; }" : "=r"(a) : "l"(p));
    return a;
}

#define CP_ASYNC16(dst_smem, src_gmem) \
    asm volatile("cp.async.cg.shared.global [%0], [%1], 16;" \
                 :: "r"((uint32_t)(dst_smem)), "l"(src_gmem) : "memory")
#define CP_COMMIT() asm volatile("cp.async.commit_group;" ::: "memory")
#define CP_WAIT(n)  asm volatile("cp.async.wait_group %0;" :: "n"(n) : "memory")

#define LDSM_X4(r0, r1, r2, r3, addr) \
    asm volatile("ldmatrix.sync.aligned.m8n8.x4.shared.b16 {%0,%1,%2,%3}, [%4];" \
                 : "=r"(r0), "=r"(r1), "=r"(r2), "=r"(r3) : "r"(addr))

#define MMA_TF32(d, a, b) \
    asm volatile( \
        "mma.sync.aligned.m16n8k8.row.col.f32.tf32.tf32.f32 " \
        "{%0,%1,%2,%3}, {%4,%5,%6,%7}, {%8,%9}, {%0,%1,%2,%3};" \
        : "+f"((d)[0]), "+f"((d)[1]), "+f"((d)[2]), "+f"((d)[3]) \
        : "r"((a)[0]), "r"((a)[1]), "r"((a)[2]), "r"((a)[3]), \
          "r"((b)[0]), "r"((b)[1]))

__device__ __forceinline__ float tf32_rn(float x) {
    uint32_t b;
    asm("cvt.rna.tf32.f32 %0, %1;" : "=r"(b) : "f"(x));
    return __uint_as_float(b);
}
__device__ __forceinline__ uint32_t tf32_rn_bits(uint32_t xb) {
    uint32_t b;
    asm("cvt.rna.tf32.f32 %0, %1;" : "=r"(b) : "f"(__uint_as_float(xb)));
    return b;
}

__device__ __forceinline__ float scale_from_exponent(const int* e) {
    int iv = *e;
    if (iv > -1000000 && iv < 1000000) return exp2f((float)iv);
    return exp2f(__int_as_float(iv));
}

// ---------------- kernel 0: zero handshake flags (each replay) ----------------
__global__ void zero_flags_kernel() {
    if (threadIdx.x < ITERS) g_flag[threadIdx.x] = 0;
}

// ---------------- fused kernel: 128 GEMM CTAs + 20 producer CTAs ----------------
__global__ void __launch_bounds__(256, 1) fused_kernel(
    const float* __restrict__ x,   // [512, 4096]
    const float4* __restrict__ U4, // [4096*4096] float4 rows
    const float* __restrict__ q,   // [4]
    const int* __restrict__ e,     // exponent
    const float* __restrict__ bias,
    float* __restrict__ out)
{
    const int bid = blockIdx.x;
    const int tid = threadIdx.x;

    if (bid >= GEMM_CTAS) {
        // ================= producer CTA: dequant W chunk-major =================
        const int p = bid - GEMM_CTAS;
        const int o_beg = p * ROWS_PER_PROD;
        const int o_end = (o_beg + ROWS_PER_PROD < OUTF) ? o_beg + ROWS_PER_PROD : OUTF;

        const float sc = scale_from_exponent(e) * (1.0f / 7.0f);
        const float t0 = q[0] * sc, t1 = q[1] * sc, t2 = q[2] * sc, t3 = q[3] * sc;

        const int row_off = tid >> 3;           // 0..31 (32 rows per pass)
        const int j = (tid & 7) * 4;            // 4 consecutive k within chunk

        #pragma unroll 1
        for (int c = 0; c < ITERS; ++c) {
            const int k0 = c * KC;
            #pragma unroll 1
            for (int o = o_beg + row_off; o < o_end; o += 32) {
                const float4* up = U4 + ((size_t)o * INF + k0 + j);
                float4 u0 = up[0], u1 = up[1], u2 = up[2], u3 = up[3];
                float4 w;
                w.x = tf32_rn(fmaf(u0.x, t0, fmaf(u0.y, t1, fmaf(u0.z, t2, u0.w * t3))));
                w.y = tf32_rn(fmaf(u1.x, t0, fmaf(u1.y, t1, fmaf(u1.z, t2, u1.w * t3))));
                w.z = tf32_rn(fmaf(u2.x, t0, fmaf(u2.y, t1, fmaf(u2.z, t2, u2.w * t3))));
                w.w = tf32_rn(fmaf(u3.x, t0, fmaf(u3.y, t1, fmaf(u3.z, t2, u3.w * t3))));
                *reinterpret_cast<float4*>(g_W + (size_t)o * INF + k0 + j) = w;
            }
            __threadfence();
            __syncthreads();
            if (tid == 0) atomicAdd(&g_flag[c], 1);
        }
        return;
    }

    // ================= consumer CTA: tf32 mma GEMM =================
    extern __shared__ float smf[];
    const uint32_t sb = smem_u32(smf);
    const int wid  = tid >> 5;
    const int lane = tid & 31;
    const int g    = lane >> 2;
    const int t    = lane & 3;
    const int wrow = wid >> 2;        // 0..1 (M)
    const int wcol = wid & 3;         // 0..3 (N)
    const int n0 = (bid & 31) * TN;   // n-tile
    const int m0 = (bid >> 5) * TM;   // m-tile

    const float* Ag = x   + (size_t)m0 * INF;
    const float* Bg = g_W + (size_t)n0 * INF;

    float acc[4][4][4];
    #pragma unroll
    for (int i = 0; i < 4; ++i)
        #pragma unroll
        for (int jj = 0; jj < 4; ++jj)
            #pragma unroll
            for (int k = 0; k < 4; ++k) acc[i][jj][k] = 0.f;

    auto poll = [&](int c) {
        int v;
        do {
            asm volatile("ld.global.acquire.gpu.b32 %0, [%1];" : "=r"(v) : "l"(g_flag + c) : "memory");
        } while (v < PROD_CTAS);
    };

    auto load_stage = [&](int it, int s) {
        const uint32_t As = sb + (uint32_t)s * STAGE_BYTES;
        const uint32_t Bs = As + TILE_FLOATS * 4;
        const int kbase = it * KC;
        #pragma unroll
        for (int i = 0; i < 4; ++i) {
            int cid = i * 256 + tid;
            int r = cid >> 3, c = cid & 7;
            CP_ASYNC16(As + (uint32_t)(r * AS_STRIDE + c * 4) * 4,
                       Ag + (size_t)r * INF + kbase + c * 4);
        }
        #pragma unroll
        for (int i = 0; i < 4; ++i) {
            int cid = i * 256 + tid;
            int r = cid >> 3, c = cid & 7;
            CP_ASYNC16(Bs + (uint32_t)(r * AS_STRIDE + c * 4) * 4,
                       Bg + (size_t)r * INF + kbase + c * 4);
        }
        CP_COMMIT();
    };

    #pragma unroll
    for (int s = 0; s < STAGES - 1; ++s) { poll(s); load_stage(s, s); }

    const int lrow  = lane & 15;
    const int lkoff = (lane >> 4) << 2;
    const uint32_t a_lane_off = (uint32_t)((wrow * 64 + lrow) * AS_STRIDE + lkoff) * 4;
    const uint32_t b_lane_off = (uint32_t)((wcol * 32 + lrow) * AS_STRIDE + lkoff) * 4;

    #pragma unroll 1
    for (int it = 0; it < ITERS; ++it) {
        CP_WAIT(STAGES - 2);
        __syncthreads();
        int nxt = it + STAGES - 1;
        if (nxt < ITERS) { poll(nxt); load_stage(nxt, nxt % STAGES); }

        const uint32_t As = sb + (uint32_t)(it % STAGES) * STAGE_BYTES;
        const uint32_t Bs = As + TILE_FLOATS * 4;

        #pragma unroll
        for (int ks = 0; ks < 4; ++ks) {
            const uint32_t k0b = (uint32_t)(ks * 8) * 4;
            uint32_t a[4][4], b[4][2];
            #pragma unroll
            for (int mt = 0; mt < 4; ++mt) {
                LDSM_X4(a[mt][0], a[mt][1], a[mt][2], a[mt][3],
                        As + a_lane_off + (uint32_t)(mt * 16 * AS_STRIDE) * 4 + k0b);
            }
            #pragma unroll
            for (int np = 0; np < 2; ++np) {
                LDSM_X4(b[2 * np][0], b[2 * np + 1][0], b[2 * np][1], b[2 * np + 1][1],
                        Bs + b_lane_off + (uint32_t)(np * 16 * AS_STRIDE) * 4 + k0b);
            }
            // round A fragments to tf32 (W is pre-rounded by producers)
            #pragma unroll
            for (int mt = 0; mt < 4; ++mt)
                #pragma unroll
                for (int r = 0; r < 4; ++r) a[mt][r] = tf32_rn_bits(a[mt][r]);
            #pragma unroll
            for (int mt = 0; mt < 4; ++mt)
                #pragma unroll
                for (int nt = 0; nt < 4; ++nt)
                    MMA_TF32(acc[mt][nt], a[mt], b[nt]);
        }
    }

    // ---- epilogue: registers -> gmem with fused bias, float2 stores ----
    #pragma unroll
    for (int nt = 0; nt < 4; ++nt) {
        const int n = n0 + wcol * 32 + nt * 8 + 2 * t;
        const float b0 = bias[n], b1 = bias[n + 1];
        #pragma unroll
        for (int mt = 0; mt < 4; ++mt) {
            const int m = m0 + wrow * 64 + mt * 16 + g;
            float2 lo = make_float2(acc[mt][nt][0] + b0, acc[mt][nt][1] + b1);
            float2 hi = make_float2(acc[mt][nt][2] + b0, acc[mt][nt][3] + b1);
            *reinterpret_cast<float2*>(out + (size_t)m * OUTF + n) = lo;
            *reinterpret_cast<float2*>(out + (size_t)(m + 8) * OUTF + n) = hi;
        }
    }
}

// ---------------- launch ----------------
extern "C" void kernel_launch(void* const* d_in, const int* in_sizes, int n_in,
                              void* d_out, int out_size)
{
    const float* x = (const float*)d_in[0];   // [512, 4096]
    const float* U = (const float*)d_in[1];   // [4096*4096, 4]
    const float* q = (const float*)d_in[2];   // [4]
    const float* b = (const float*)d_in[3];   // [4096]
    const int*   e = (const int*)d_in[4];     // exponent scalar

    cudaFuncSetAttribute(fused_kernel,
                         cudaFuncAttributeMaxDynamicSharedMemorySize, SMEM_BYTES);

    zero_flags_kernel<<<1, 128>>>();
    fused_kernel<<<GEMM_CTAS + PROD_CTAS, 256, SMEM_BYTES>>>(
        x, (const float4*)U, q, e, b, (float*)d_out);
}

// round 6
// speedup vs baseline: 5.7040x; 5.7040x over previous
#include <cuda_runtime.h>
#include <cuda_fp16.h>
#include <cstdint>

// Problem constants
#define BATCH 512
#define INF   4096
#define OUTF  4096

// GEMM tiling: CTA 128x128, K-chunk 64 halves (128B rows). Warp grid 2(M) x 4(N).
#define TM 128
#define TN 128
#define KC 64                      // halves per K-chunk
#define ITERS (INF / KC)           // 64
#define STAGES 4
#define AS_STRIDE 72               // halves per smem row (64 + 8 pad) -> conflict-free LDSM
#define TILE_HALVES (128 * AS_STRIDE)            // 9216 halves = 18432 B
#define STAGE_BYTES (2 * TILE_HALVES * 2)        // A + B = 36864 B
#define SMEM_BYTES (STAGES * STAGE_BYTES)        // 147456 B

// Scratch (device globals are the sanctioned scratch mechanism)
__device__ __half g_W[(size_t)OUTF * INF];   // dequantized weight, fp16 (32 MB)
__device__ __half g_x[(size_t)BATCH * INF];  // x, fp16 (4 MB)

// ---------------- PTX helpers (plain-sm_103 legal) ----------------
__device__ __forceinline__ uint32_t smem_u32(const void* p) {
    uint32_t a;
    asm("{ .reg .u64 t; cvta.to.shared.u64 t, %1; cvt.u32.u64 %0, t; }" : "=r"(a) : "l"(p));
    return a;
}

#define CP_ASYNC16(dst_smem, src_gmem) \
    asm volatile("cp.async.cg.shared.global [%0], [%1], 16;" \
                 :: "r"((uint32_t)(dst_smem)), "l"(src_gmem) : "memory")
#define CP_COMMIT() asm volatile("cp.async.commit_group;" ::: "memory")
#define CP_WAIT(n)  asm volatile("cp.async.wait_group %0;" :: "n"(n) : "memory")

#define LDSM_X4(r0, r1, r2, r3, addr) \
    asm volatile("ldmatrix.sync.aligned.m8n8.x4.shared.b16 {%0,%1,%2,%3}, [%4];" \
                 : "=r"(r0), "=r"(r1), "=r"(r2), "=r"(r3) : "r"(addr))

// mma.sync m16n8k16 f16 with f32 accumulate (sm_80 baseline)
#define MMA_F16(d, a, b) \
    asm volatile( \
        "mma.sync.aligned.m16n8k16.row.col.f32.f16.f16.f32 " \
        "{%0,%1,%2,%3}, {%4,%5,%6,%7}, {%8,%9}, {%0,%1,%2,%3};" \
        : "+f"((d)[0]), "+f"((d)[1]), "+f"((d)[2]), "+f"((d)[3]) \
        : "r"((a)[0]), "r"((a)[1]), "r"((a)[2]), "r"((a)[3]), \
          "r"((b)[0]), "r"((b)[1]))

__device__ __forceinline__ float scale_from_exponent(const int* e) {
    int iv = *e;
    if (iv > -1000000 && iv < 1000000) return exp2f((float)iv);
    return exp2f(__int_as_float(iv));
}

// ---------------- kernel 1: dequant W = (U @ t_hat) -> fp16 ----------------
// Each thread: 8 consecutive W elements (reads 8 float4 = 128B, writes 16B).
__global__ void __launch_bounds__(256) prep_w_kernel(
    const float4* __restrict__ U4, const float* __restrict__ q, const int* __restrict__ e)
{
    const float sc = scale_from_exponent(e) * (1.0f / 7.0f);
    const float t0 = q[0] * sc, t1 = q[1] * sc, t2 = q[2] * sc, t3 = q[3] * sc;

    size_t t = (size_t)blockIdx.x * 256 + threadIdx.x;   // 0 .. 2097151
    const float4* u = U4 + (t << 3);
    __half h[8];
    #pragma unroll
    for (int i = 0; i < 8; ++i) {
        float4 v = u[i];
        h[i] = __float2half_rn(fmaf(v.x, t0, fmaf(v.y, t1, fmaf(v.z, t2, v.w * t3))));
    }
    *reinterpret_cast<uint4*>(g_W + (t << 3)) = *reinterpret_cast<uint4*>(h);
}

// ---------------- kernel 2: convert x to fp16 ----------------
__global__ void __launch_bounds__(256) conv_x_kernel(const float4* __restrict__ x4)
{
    size_t t = (size_t)blockIdx.x * 256 + threadIdx.x;   // 0 .. 262143
    float4 a = x4[2 * t], b = x4[2 * t + 1];
    __half h[8];
    h[0] = __float2half_rn(a.x); h[1] = __float2half_rn(a.y);
    h[2] = __float2half_rn(a.z); h[3] = __float2half_rn(a.w);
    h[4] = __float2half_rn(b.x); h[5] = __float2half_rn(b.y);
    h[6] = __float2half_rn(b.z); h[7] = __float2half_rn(b.w);
    *reinterpret_cast<uint4*>(g_x + (t << 3)) = *reinterpret_cast<uint4*>(h);
}

// ---------------- kernel 3: fp16 mma.sync GEMM: y = x @ W^T + b ----------------
__global__ void __launch_bounds__(256, 1) gemm_f16_kernel(
    const float* __restrict__ bias, float* __restrict__ out)
{
    extern __shared__ __half smh[];
    const uint32_t sb = smem_u32(smh);
    const int tid  = threadIdx.x;
    const int wid  = tid >> 5;
    const int lane = tid & 31;
    const int g    = lane >> 2;       // groupID
    const int t    = lane & 3;        // thread-in-group
    const int wrow = wid >> 2;        // 0..1 (M)
    const int wcol = wid & 3;         // 0..3 (N)
    const int m0 = blockIdx.y * TM;
    const int n0 = blockIdx.x * TN;

    const __half* Ag = g_x + (size_t)m0 * INF;
    const __half* Bg = g_W + (size_t)n0 * INF;

    float acc[4][4][4];
    #pragma unroll
    for (int i = 0; i < 4; ++i)
        #pragma unroll
        for (int j = 0; j < 4; ++j)
            #pragma unroll
            for (int k = 0; k < 4; ++k) acc[i][j][k] = 0.f;

    // A/B tile rows: 128 rows x 128B (8 x 16B segments); smem row stride 144B.
    auto load_stage = [&](int it, int s) {
        const uint32_t As = sb + (uint32_t)s * STAGE_BYTES;
        const uint32_t Bs = As + TILE_HALVES * 2;
        const int kbase = it * KC;
        #pragma unroll
        for (int i = 0; i < 4; ++i) {
            int cid = i * 256 + tid;
            int r = cid >> 3, c = cid & 7;
            CP_ASYNC16(As + (uint32_t)(r * AS_STRIDE + c * 8) * 2,
                       Ag + (size_t)r * INF + kbase + c * 8);
        }
        #pragma unroll
        for (int i = 0; i < 4; ++i) {
            int cid = i * 256 + tid;
            int r = cid >> 3, c = cid & 7;
            CP_ASYNC16(Bs + (uint32_t)(r * AS_STRIDE + c * 8) * 2,
                       Bg + (size_t)r * INF + kbase + c * 8);
        }
        CP_COMMIT();
    };

    #pragma unroll
    for (int s = 0; s < STAGES - 1; ++s) load_stage(s, s);

    // A ldmatrix lane pattern: row = base + (lane&15), k-halves offset (lane>>4)*8
    const uint32_t a_lane_off =
        (uint32_t)((wrow * 64 + (lane & 15)) * AS_STRIDE + ((lane >> 4) << 3)) * 2;
    // B ldmatrix lane pattern: row = base + (lane>>4)*8 + (lane&7), koff = ((lane>>3)&1)*8
    const uint32_t b_lane_off =
        (uint32_t)((wcol * 32 + ((lane >> 4) << 3) + (lane & 7)) * AS_STRIDE +
                   (((lane >> 3) & 1) << 3)) * 2;

    #pragma unroll 1
    for (int it = 0; it < ITERS; ++it) {
        CP_WAIT(STAGES - 2);
        __syncthreads();
        int nxt = it + STAGES - 1;
        if (nxt < ITERS) load_stage(nxt, nxt % STAGES);

        const uint32_t As = sb + (uint32_t)(it % STAGES) * STAGE_BYTES;
        const uint32_t Bs = As + TILE_HALVES * 2;

        #pragma unroll
        for (int ks = 0; ks < 4; ++ks) {           // 4 x k16 per chunk
            const uint32_t k0b = (uint32_t)(ks * 16) * 2;
            uint32_t a[4][4], b[4][2];
            #pragma unroll
            for (int mt = 0; mt < 4; ++mt) {
                LDSM_X4(a[mt][0], a[mt][1], a[mt][2], a[mt][3],
                        As + a_lane_off + (uint32_t)(mt * 16 * AS_STRIDE) * 2 + k0b);
            }
            #pragma unroll
            for (int np = 0; np < 2; ++np) {       // two n-tile pairs
                LDSM_X4(b[2 * np][0], b[2 * np][1], b[2 * np + 1][0], b[2 * np + 1][1],
                        Bs + b_lane_off + (uint32_t)(np * 16 * AS_STRIDE) * 2 + k0b);
            }
            #pragma unroll
            for (int mt = 0; mt < 4; ++mt)
                #pragma unroll
                for (int nt = 0; nt < 4; ++nt)
                    MMA_F16(acc[mt][nt], a[mt], b[nt]);
        }
    }

    // ---- epilogue: registers -> gmem with fused bias, float2 stores ----
    #pragma unroll
    for (int nt = 0; nt < 4; ++nt) {
        const int n = n0 + wcol * 32 + nt * 8 + 2 * t;
        const float b0 = bias[n], b1 = bias[n + 1];
        #pragma unroll
        for (int mt = 0; mt < 4; ++mt) {
            const int m = m0 + wrow * 64 + mt * 16 + g;
            float2 lo = make_float2(acc[mt][nt][0] + b0, acc[mt][nt][1] + b1);
            float2 hi = make_float2(acc[mt][nt][2] + b0, acc[mt][nt][3] + b1);
            *reinterpret_cast<float2*>(out + (size_t)m * OUTF + n) = lo;
            *reinterpret_cast<float2*>(out + (size_t)(m + 8) * OUTF + n) = hi;
        }
    }
}

// ---------------- launch ----------------
extern "C" void kernel_launch(void* const* d_in, const int* in_sizes, int n_in,
                              void* d_out, int out_size)
{
    const float* x = (const float*)d_in[0];   // [512, 4096]
    const float* U = (const float*)d_in[1];   // [4096*4096, 4]
    const float* q = (const float*)d_in[2];   // [4]
    const float* b = (const float*)d_in[3];   // [4096]
    const int*   e = (const int*)d_in[4];     // exponent scalar

    cudaFuncSetAttribute(gemm_f16_kernel,
                         cudaFuncAttributeMaxDynamicSharedMemorySize, SMEM_BYTES);

    prep_w_kernel<<<8192, 256>>>((const float4*)U, q, e);   // 16.7M W elems / 8 per thread
    conv_x_kernel<<<1024, 256>>>((const float4*)x);         // 2.1M x elems / 8 per thread
    gemm_f16_kernel<<<dim3(OUTF / TN, BATCH / TM), 256, SMEM_BYTES>>>(b, (float*)d_out);
}

// round 7
// speedup vs baseline: 6.3876x; 1.1199x over previous
#include <cuda_runtime.h>
#include <cuda_fp16.h>
#include <cstdint>

// Problem constants
#define BATCH 512
#define INF   4096
#define OUTF  4096

// GEMM tiling: CTA 128x128, K-chunk 64 halves (128B rows). Warp grid 2(M) x 4(N).
#define TM 128
#define TN 128
#define KC 64                      // halves per K-chunk
#define ITERS (INF / KC)           // 64
#define STAGES 4
#define AS_STRIDE 72               // halves per smem row (64 + 8 pad) -> conflict-free LDSM
#define TILE_HALVES (128 * AS_STRIDE)            // 9216 halves = 18432 B
#define STAGE_BYTES (2 * TILE_HALVES * 2)        // A + B = 36864 B
#define SMEM_BYTES (STAGES * STAGE_BYTES)        // 147456 B

// Scratch (device globals are the sanctioned scratch mechanism)
__device__ __half g_W[(size_t)OUTF * INF];   // dequantized weight, fp16 (32 MB)
__device__ __half g_x[(size_t)BATCH * INF];  // x, fp16 (4 MB)

// ---------------- PTX helpers (plain-sm_103 legal) ----------------
__device__ __forceinline__ uint32_t smem_u32(const void* p) {
    uint32_t a;
    asm("{ .reg .u64 t; cvta.to.shared.u64 t, %1; cvt.u32.u64 %0, t; }" : "=r"(a) : "l"(p));
    return a;
}

#define CP_ASYNC16(dst_smem, src_gmem) \
    asm volatile("cp.async.cg.shared.global [%0], [%1], 16;" \
                 :: "r"((uint32_t)(dst_smem)), "l"(src_gmem) : "memory")
#define CP_COMMIT() asm volatile("cp.async.commit_group;" ::: "memory")
#define CP_WAIT(n)  asm volatile("cp.async.wait_group %0;" :: "n"(n) : "memory")

#define LDSM_X4(r0, r1, r2, r3, addr) \
    asm volatile("ldmatrix.sync.aligned.m8n8.x4.shared.b16 {%0,%1,%2,%3}, [%4];" \
                 : "=r"(r0), "=r"(r1), "=r"(r2), "=r"(r3) : "r"(addr))

// mma.sync m16n8k16 f16 with f32 accumulate (sm_80 baseline)
#define MMA_F16(d, a, b) \
    asm volatile( \
        "mma.sync.aligned.m16n8k16.row.col.f32.f16.f16.f32 " \
        "{%0,%1,%2,%3}, {%4,%5,%6,%7}, {%8,%9}, {%0,%1,%2,%3};" \
        : "+f"((d)[0]), "+f"((d)[1]), "+f"((d)[2]), "+f"((d)[3]) \
        : "r"((a)[0]), "r"((a)[1]), "r"((a)[2]), "r"((a)[3]), \
          "r"((b)[0]), "r"((b)[1]))

__device__ __forceinline__ float scale_from_exponent(const int* e) {
    int iv = *e;
    if (iv > -1000000 && iv < 1000000) return exp2f((float)iv);
    return exp2f(__int_as_float(iv));
}

// ---------------- kernel 1: dequant W = (U @ t_hat) -> fp16, fully coalesced ----
// Block handles 2048 consecutive W elements. Iteration i: lanes read ADJACENT
// float4s (512B/warp-instr = 4 lines) and store 64 contiguous bytes of halves.
__global__ void __launch_bounds__(256) prep_w_kernel(
    const float4* __restrict__ U4, const float* __restrict__ q, const int* __restrict__ e)
{
    const float sc = scale_from_exponent(e) * (1.0f / 7.0f);
    const float t0 = q[0] * sc, t1 = q[1] * sc, t2 = q[2] * sc, t3 = q[3] * sc;

    const size_t base = (size_t)blockIdx.x * 2048 + threadIdx.x;
    float4 v[8];
    #pragma unroll
    for (int i = 0; i < 8; ++i) v[i] = U4[base + i * 256];      // MLP=8, coalesced
    #pragma unroll
    for (int i = 0; i < 8; ++i) {
        g_W[base + i * 256] =
            __float2half_rn(fmaf(v[i].x, t0, fmaf(v[i].y, t1, fmaf(v[i].z, t2, v[i].w * t3))));
    }
}

// ---------------- kernel 2: convert x to fp16 ----------------
__global__ void __launch_bounds__(256) conv_x_kernel(const float4* __restrict__ x4)
{
    // Block handles 2048 consecutive x elements; same coalesced shape as prep.
    const size_t base = (size_t)blockIdx.x * 2048 + threadIdx.x;
    #pragma unroll
    for (int i = 0; i < 8; ++i) {
        float4 v = x4[base + i * 256];
        g_x[base + i * 256] =
            __float2half_rn(v.x);   // NOTE: x4 holds 4 floats -> this maps 1:1 below
    }
}

// conv_x above is wrong shape on purpose? No — x has 2.1M elements = 524288 float4.
// Rewritten properly as an element-wise kernel over floats:
__global__ void __launch_bounds__(256) conv_x_kernel2(const float* __restrict__ xf)
{
    const size_t base = (size_t)blockIdx.x * 2048 + threadIdx.x;
    #pragma unroll
    for (int i = 0; i < 8; ++i) {
        size_t idx = base + i * 256;
        g_x[idx] = __float2half_rn(xf[idx]);
    }
}

// ---------------- kernel 3: fp16 mma.sync GEMM: y = x @ W^T + b ----------------
__global__ void __launch_bounds__(256, 1) gemm_f16_kernel(
    const float* __restrict__ bias, float* __restrict__ out)
{
    extern __shared__ __half smh[];
    const uint32_t sb = smem_u32(smh);
    const int tid  = threadIdx.x;
    const int wid  = tid >> 5;
    const int lane = tid & 31;
    const int g    = lane >> 2;       // groupID
    const int t    = lane & 3;        // thread-in-group
    const int wrow = wid >> 2;        // 0..1 (M)
    const int wcol = wid & 3;         // 0..3 (N)
    const int m0 = blockIdx.y * TM;
    const int n0 = blockIdx.x * TN;

    const __half* Ag = g_x + (size_t)m0 * INF;
    const __half* Bg = g_W + (size_t)n0 * INF;

    float acc[4][4][4];
    #pragma unroll
    for (int i = 0; i < 4; ++i)
        #pragma unroll
        for (int j = 0; j < 4; ++j)
            #pragma unroll
            for (int k = 0; k < 4; ++k) acc[i][j][k] = 0.f;

    auto load_stage = [&](int it, int s) {
        const uint32_t As = sb + (uint32_t)s * STAGE_BYTES;
        const uint32_t Bs = As + TILE_HALVES * 2;
        const int kbase = it * KC;
        #pragma unroll
        for (int i = 0; i < 4; ++i) {
            int cid = i * 256 + tid;
            int r = cid >> 3, c = cid & 7;
            CP_ASYNC16(As + (uint32_t)(r * AS_STRIDE + c * 8) * 2,
                       Ag + (size_t)r * INF + kbase + c * 8);
        }
        #pragma unroll
        for (int i = 0; i < 4; ++i) {
            int cid = i * 256 + tid;
            int r = cid >> 3, c = cid & 7;
            CP_ASYNC16(Bs + (uint32_t)(r * AS_STRIDE + c * 8) * 2,
                       Bg + (size_t)r * INF + kbase + c * 8);
        }
        CP_COMMIT();
    };

    #pragma unroll
    for (int s = 0; s < STAGES - 1; ++s) load_stage(s, s);

    const uint32_t a_lane_off =
        (uint32_t)((wrow * 64 + (lane & 15)) * AS_STRIDE + ((lane >> 4) << 3)) * 2;
    const uint32_t b_lane_off =
        (uint32_t)((wcol * 32 + ((lane >> 4) << 3) + (lane & 7)) * AS_STRIDE +
                   (((lane >> 3) & 1) << 3)) * 2;

    #pragma unroll 1
    for (int it = 0; it < ITERS; ++it) {
        CP_WAIT(STAGES - 2);
        __syncthreads();
        int nxt = it + STAGES - 1;
        if (nxt < ITERS) load_stage(nxt, nxt % STAGES);

        const uint32_t As = sb + (uint32_t)(it % STAGES) * STAGE_BYTES;
        const uint32_t Bs = As + TILE_HALVES * 2;

        #pragma unroll
        for (int ks = 0; ks < 4; ++ks) {
            const uint32_t k0b = (uint32_t)(ks * 16) * 2;
            uint32_t a[4][4], b[4][2];
            #pragma unroll
            for (int mt = 0; mt < 4; ++mt) {
                LDSM_X4(a[mt][0], a[mt][1], a[mt][2], a[mt][3],
                        As + a_lane_off + (uint32_t)(mt * 16 * AS_STRIDE) * 2 + k0b);
            }
            #pragma unroll
            for (int np = 0; np < 2; ++np) {
                LDSM_X4(b[2 * np][0], b[2 * np][1], b[2 * np + 1][0], b[2 * np + 1][1],
                        Bs + b_lane_off + (uint32_t)(np * 16 * AS_STRIDE) * 2 + k0b);
            }
            #pragma unroll
            for (int mt = 0; mt < 4; ++mt)
                #pragma unroll
                for (int nt = 0; nt < 4; ++nt)
                    MMA_F16(acc[mt][nt], a[mt], b[nt]);
        }
    }

    // ---- epilogue: registers -> gmem with fused bias, float2 stores ----
    #pragma unroll
    for (int nt = 0; nt < 4; ++nt) {
        const int n = n0 + wcol * 32 + nt * 8 + 2 * t;
        const float b0 = bias[n], b1 = bias[n + 1];
        #pragma unroll
        for (int mt = 0; mt < 4; ++mt) {
            const int m = m0 + wrow * 64 + mt * 16 + g;
            float2 lo = make_float2(acc[mt][nt][0] + b0, acc[mt][nt][1] + b1);
            float2 hi = make_float2(acc[mt][nt][2] + b0, acc[mt][nt][3] + b1);
            *reinterpret_cast<float2*>(out + (size_t)m * OUTF + n) = lo;
            *reinterpret_cast<float2*>(out + (size_t)(m + 8) * OUTF + n) = hi;
        }
    }
}

// ---------------- launch ----------------
extern "C" void kernel_launch(void* const* d_in, const int* in_sizes, int n_in,
                              void* d_out, int out_size)
{
    const float* x = (const float*)d_in[0];   // [512, 4096]
    const float* U = (const float*)d_in[1];   // [4096*4096, 4]
    const float* q = (const float*)d_in[2];   // [4]
    const float* b = (const float*)d_in[3];   // [4096]
    const int*   e = (const int*)d_in[4];     // exponent scalar

    cudaFuncSetAttribute(gemm_f16_kernel,
                         cudaFuncAttributeMaxDynamicSharedMemorySize, SMEM_BYTES);

    prep_w_kernel<<<8192, 256>>>((const float4*)U, q, e);   // 16.7M W elems, 2048/block
    conv_x_kernel2<<<1024, 256>>>(x);                        // 2.1M x elems, 2048/block
    gemm_f16_kernel<<<dim3(OUTF / TN, BATCH / TM), 256, SMEM_BYTES>>>(b, (float*)d_out);
}